// round 16
// baseline (speedup 1.0000x reference)
#include <cuda_runtime.h>
#include <cuda_fp16.h>

// ============================================================================
// AttentionGate3D — round 16: round-13 (best, 244.2us) with the tail tuned:
//  - k_combine: uint4 (16B) loads, 8 points/thread  (was uint2/4 pts)
//  - k_mul: 8 elements/thread, both loads ahead of the sigmoid chain
//  - launch order puts k_combine at ncu slot 4 for evidence next round
// Fused GEMM byte-identical to round 13.
// ============================================================================

#define EPS 1e-5f

constexpr int NB = 2;
constexpr int G  = 256;
constexpr int XC = 128;
constexpr int I  = 128;
constexpr int S  = 32 * 64 * 64;   // 131072

// ---- scratch ----
__device__ __half d_yg[NB * I * S];
__device__ __half d_yx[NB * I * S];
__device__ __align__(16) __half d_whg[I * G];
__device__ __align__(16) __half d_whx[I * XC];
__device__ float  d_z[NB * S];
__device__ float  d_sum_g[NB * I];
__device__ float  d_sq_g [NB * I];
__device__ float  d_sum_x[NB * I];
__device__ float  d_sq_x [NB * I];
__device__ float  d_zstat[2 * NB];

// ---- prologue (2 launches; gemm=3rd, combine=4th = ncu slot) ----
__global__ void k_wconv_g(const float* __restrict__ Wg) {
    int t = blockIdx.x * 256 + threadIdx.x;
    if (t < I * G) d_whg[t] = __float2half_rn(Wg[t]);
}
__global__ void k_wconv_x_zero(const float* __restrict__ Wx) {
    int t = blockIdx.x * 256 + threadIdx.x;
    if (t < I * XC) d_whx[t] = __float2half_rn(Wx[t]);
    if (t < NB * I) {
        d_sum_g[t] = 0.f; d_sq_g[t] = 0.f;
        d_sum_x[t] = 0.f; d_sq_x[t] = 0.f;
    }
    if (t < 2 * NB) d_zstat[t] = 0.f;
}

// ---- MMA helpers ----
__device__ __forceinline__ void ldsm_x4(unsigned (&r)[4], unsigned addr) {
    asm volatile("ldmatrix.sync.aligned.m8n8.x4.shared.b16 {%0,%1,%2,%3}, [%4];"
        : "=r"(r[0]), "=r"(r[1]), "=r"(r[2]), "=r"(r[3]) : "r"(addr));
}
__device__ __forceinline__ void ldsm_x4_t(unsigned (&r)[4], unsigned addr) {
    asm volatile("ldmatrix.sync.aligned.m8n8.x4.trans.shared.b16 {%0,%1,%2,%3}, [%4];"
        : "=r"(r[0]), "=r"(r[1]), "=r"(r[2]), "=r"(r[3]) : "r"(addr));
}
__device__ __forceinline__ void mma16816(float (&d)[4], const unsigned (&a)[4],
                                         const unsigned (&b)[2]) {
    asm volatile("mma.sync.aligned.m16n8k16.row.col.f32.f16.f16.f32 "
        "{%0,%1,%2,%3}, {%4,%5,%6,%7}, {%8,%9}, {%0,%1,%2,%3};"
        : "+f"(d[0]), "+f"(d[1]), "+f"(d[2]), "+f"(d[3])
        : "r"(a[0]), "r"(a[1]), "r"(a[2]), "r"(a[3]), "r"(b[0]), "r"(b[1]));
}
union H2U { __half2 h; unsigned u; };
__device__ __forceinline__ unsigned pack2h(float a, float b) {
    H2U v; v.h = __floats2half2_rn(a, b); return v.u;
}
__device__ __forceinline__ void cp16(unsigned dst, const void* src) {
    asm volatile("cp.async.cg.shared.global [%0], [%1], 16;" :: "r"(dst), "l"(src));
}
__device__ __forceinline__ void cp_commit() {
    asm volatile("cp.async.commit_group;" ::: "memory");
}
template<int N>
__device__ __forceinline__ void cp_wait() {
    asm volatile("cp.async.wait_group %0;" :: "n"(N) : "memory");
}

// ---- GEMM body (round-9/13, verbatim) --------------------------------------
template<int K, bool ISG>
__device__ __forceinline__ void gemm_body(const float* __restrict__ src,
                                          char* smem, int n, int p0) {
    constexpr int NIT2 = K / 32;
    const unsigned sS32  = (unsigned)__cvta_generic_to_shared(smem);
    const unsigned sAh32 = (unsigned)__cvta_generic_to_shared(smem + 49152);
    const unsigned sBh32 = (unsigned)__cvta_generic_to_shared(smem + 81920);
    float*  sS  = reinterpret_cast<float*>(smem);
    __half* sBh = reinterpret_cast<__half*>(smem + 81920);

    const __half* wh  = ISG ? d_whg   : d_whx;
    __half* yout = ISG ? d_yg    : d_yx;
    float*  ssum = ISG ? d_sum_g : d_sum_x;
    float*  ssq  = ISG ? d_sq_g  : d_sq_x;

    const int tid  = threadIdx.x;
    const int warp = tid >> 5, lane = tid & 31;
    const int wm = warp >> 2, wn = warp & 3;
    const float* srcn = src + (size_t)n * K * S + p0;

    const int cst = tid >> 4;
    const int pb  = tid & 15;
    const float* gp = srcn + (size_t)cst * S + pb * 4;
    const unsigned myoffB = (unsigned)(cst * 512 + pb * 16);
    const int arow = tid >> 1, ah = tid & 1;
    const __half* wsrc = wh + (size_t)arow * K + ah * 8;
    const unsigned myoffA = (unsigned)(arow * 16);

    auto issue = [&](int it) {
        unsigned dstB = sS32 + (unsigned)((it % 3) * 16384) + myoffB;
        const float* s0 = gp + (size_t)it * 32 * S;
        cp16(dstB, s0);
        cp16(dstB + 256, s0 + 64);
        cp16(dstB + 8192, s0 + (size_t)16 * S);
        cp16(dstB + 8192 + 256, s0 + (size_t)16 * S + 64);
        unsigned dstA = sAh32 + (unsigned)((it & 3) * 8192) + myoffA;
        const __half* w0 = wsrc + it * 32;
        cp16(dstA + ah * 2048, w0);
        cp16(dstA + (2 + ah) * 2048, w0 + 16);
    };

    issue(0); cp_commit();
    issue(1); cp_commit();
    issue(2); cp_commit();

    float acc[4][4][4] = {};

    const int swz  = ((pb >> 1) ^ (cst & 7));
    const int sts0 = (cst * 128 + (swz << 3)       + ((pb & 1) << 2)) * 2;
    const int sts1 = (cst * 128 + ((8 + swz) << 3) + ((pb & 1) << 2)) * 2;

    for (int it = 0; it < NIT2; it++) {
        cp_wait<2>();
        const float4* rp = reinterpret_cast<const float4*>(
            sS + (it % 3) * 4096 + cst * 128 + pb * 4);
        float4 w0 = rp[0];
        float4 w1 = rp[16];
        float4 w2 = rp[512];
        float4 w3 = rp[528];
        {
            char* sb = reinterpret_cast<char*>(sBh) + (it & 1) * 8192;
            uint2 u;
            u.x = pack2h(w0.x, w0.y); u.y = pack2h(w0.z, w0.w);
            *reinterpret_cast<uint2*>(sb + sts0) = u;
            u.x = pack2h(w1.x, w1.y); u.y = pack2h(w1.z, w1.w);
            *reinterpret_cast<uint2*>(sb + sts1) = u;
            u.x = pack2h(w2.x, w2.y); u.y = pack2h(w2.z, w2.w);
            *reinterpret_cast<uint2*>(sb + 4096 + sts0) = u;
            u.x = pack2h(w3.x, w3.y); u.y = pack2h(w3.z, w3.w);
            *reinterpret_cast<uint2*>(sb + 4096 + sts1) = u;
        }
        __syncthreads();
        if (it + 3 < NIT2) issue(it + 3);
        cp_commit();

        const unsigned sbb = sBh32 + (unsigned)((it & 1) * 8192);
        const unsigned saa = sAh32 + (unsigned)((it & 3) * 8192);
#pragma unroll
        for (int kh2 = 0; kh2 < 2; kh2++) {
            unsigned afr[4][4];
#pragma unroll
            for (int tm = 0; tm < 4; tm++) {
                int row = wm * 64 + tm * 16 + (lane & 15);
                ldsm_x4(afr[tm], saa + (unsigned)(kh2 * 4096 +
                         (lane >> 4) * 2048 + row * 16));
            }
            unsigned bfr[4][2];
#pragma unroll
            for (int h = 0; h < 2; h++) {
                int nbX  = 2 * h + ((lane >> 4) & 1);
                int c    = ((lane >> 3) & 1) * 8 + (lane & 7);
                int phys = (wn * 4 + nbX) ^ (lane & 7);
                unsigned r4[4];
                ldsm_x4_t(r4, sbb + (unsigned)(kh2 * 4096 +
                          (c * 128 + phys * 8) * 2));
                bfr[2 * h][0]     = r4[0]; bfr[2 * h][1]     = r4[1];
                bfr[2 * h + 1][0] = r4[2]; bfr[2 * h + 1][1] = r4[3];
            }
#pragma unroll
            for (int tm = 0; tm < 4; tm++)
#pragma unroll
                for (int tn = 0; tn < 4; tn++)
                    mma16816(acc[tm][tn], afr[tm], bfr[tn]);
        }
    }

    __half* yn = yout + (size_t)n * I * S + p0;
#pragma unroll
    for (int tm = 0; tm < 4; tm++) {
        int r1 = wm * 64 + tm * 16 + (lane >> 2);
        float s1 = 0.f, q1 = 0.f, s2 = 0.f, q2 = 0.f;
#pragma unroll
        for (int tn = 0; tn < 4; tn++) {
            float* c = acc[tm][tn];
            int col = wn * 32 + tn * 8 + (lane & 3) * 2;
            *reinterpret_cast<__half2*>(yn + (size_t)r1 * S + col) =
                __floats2half2_rn(c[0], c[1]);
            *reinterpret_cast<__half2*>(yn + (size_t)(r1 + 8) * S + col) =
                __floats2half2_rn(c[2], c[3]);
            s1 += c[0] + c[1]; q1 += c[0] * c[0] + c[1] * c[1];
            s2 += c[2] + c[3]; q2 += c[2] * c[2] + c[3] * c[3];
        }
#pragma unroll
        for (int off = 2; off > 0; off >>= 1) {
            s1 += __shfl_down_sync(0xFFFFFFFFu, s1, off, 4);
            q1 += __shfl_down_sync(0xFFFFFFFFu, q1, off, 4);
            s2 += __shfl_down_sync(0xFFFFFFFFu, s2, off, 4);
            q2 += __shfl_down_sync(0xFFFFFFFFu, q2, off, 4);
        }
        if ((lane & 3) == 0) {
            atomicAdd(&ssum[n * I + r1], s1);
            atomicAdd(&ssq [n * I + r1], q1);
            atomicAdd(&ssum[n * I + r1 + 8], s2);
            atomicAdd(&ssq [n * I + r1 + 8], q2);
        }
    }
}

// ---- fused GEMM: even bx -> x-GEMM, odd bx -> g-GEMM (1024 tiles each) ----
__global__ void __launch_bounds__(256, 2) k_gemm_fused(const float* __restrict__ g,
                                                       const float* __restrict__ x) {
    extern __shared__ __align__(16) char smem[];
    const int bx = blockIdx.x;
    const int n  = blockIdx.y;
    const int p0 = (bx >> 1) * 128;
    if ((bx & 1) == 0) {
        gemm_body<XC, false>(x, smem, n, p0);
    } else {
        gemm_body<G, true>(g, smem, n, p0);
    }
}

// ---- combine: 8 pts/thread, uint4 loads; coefs per-block; + z stats --------
__global__ void __launch_bounds__(256) k_combine(
        const float* __restrict__ Wpsi,
        const float* __restrict__ gam_g, const float* __restrict__ bet_g,
        const float* __restrict__ gam_x, const float* __restrict__ bet_x) {
    __shared__ float sc[5 * I];
    const int tid = threadIdx.x;
    const int n   = blockIdx.y;
    const int p0  = blockIdx.x * 2048;
    if (tid < I) {
        const float inv = 1.f / (float)S;
        float m   = d_sum_g[n * I + tid] * inv;
        float var = fmaxf(d_sq_g[n * I + tid] * inv - m * m, 0.f);
        float A   = gam_g[tid] * rsqrtf(var + EPS);
        sc[tid]     = A;
        sc[I + tid] = bet_g[tid] - m * A;
        m   = d_sum_x[n * I + tid] * inv;
        var = fmaxf(d_sq_x[n * I + tid] * inv - m * m, 0.f);
        A   = gam_x[tid] * rsqrtf(var + EPS);
        sc[2 * I + tid] = A;
        sc[3 * I + tid] = bet_x[tid] - m * A;
        sc[4 * I + tid] = Wpsi[tid];
    }
    __syncthreads();
    const __half* ygb = d_yg + (size_t)n * I * S + p0 + tid * 8;
    const __half* yxb = d_yx + (size_t)n * I * S + p0 + tid * 8;
    float za[8] = {};

#pragma unroll 2
    for (int i = 0; i < I; i++) {
        uint4 ua = *reinterpret_cast<const uint4*>(ygb + (size_t)i * S);
        uint4 ub = *reinterpret_cast<const uint4*>(yxb + (size_t)i * S);
        float Ag = sc[i], Ax = sc[2 * I + i];
        float C  = sc[I + i] + sc[3 * I + i];
        float w  = sc[4 * I + i];
        const unsigned* pa = &ua.x;
        const unsigned* pb = &ub.x;
#pragma unroll
        for (int q = 0; q < 4; q++) {
            H2U ha, hb; ha.u = pa[q]; hb.u = pb[q];
            float2 fa = __half22float2(ha.h);
            float2 fb = __half22float2(hb.h);
            za[2 * q]     += w * fmaxf(fmaf(Ag, fa.x, fmaf(Ax, fb.x, C)), 0.f);
            za[2 * q + 1] += w * fmaxf(fmaf(Ag, fa.y, fmaf(Ax, fb.y, C)), 0.f);
        }
    }
    float4* zp = reinterpret_cast<float4*>(&d_z[n * S + p0 + tid * 8]);
    zp[0] = make_float4(za[0], za[1], za[2], za[3]);
    zp[1] = make_float4(za[4], za[5], za[6], za[7]);

    float s = 0.f, q = 0.f;
#pragma unroll
    for (int j = 0; j < 8; j++) { s += za[j]; q += za[j] * za[j]; }
#pragma unroll
    for (int off = 16; off > 0; off >>= 1) {
        s += __shfl_down_sync(0xFFFFFFFFu, s, off);
        q += __shfl_down_sync(0xFFFFFFFFu, q, off);
    }
    __shared__ float rs[8], rq[8];
    int wid = tid >> 5, ln = tid & 31;
    if (ln == 0) { rs[wid] = s; rq[wid] = q; }
    __syncthreads();
    if (tid == 0) {
        float st = 0.f, qt = 0.f;
#pragma unroll
        for (int w2 = 0; w2 < 8; w2++) { st += rs[w2]; qt += rq[w2]; }
        atomicAdd(&d_zstat[n], st);
        atomicAdd(&d_zstat[NB + n], qt);
    }
}

// ---- fused alpha+mul: 8 elts/thread, loads ahead of the sigmoid chain ------
__global__ void k_mul(const float* __restrict__ x, float* __restrict__ out,
                      const float* __restrict__ gam_p, const float* __restrict__ bet_p) {
    const int idx = blockIdx.x * blockDim.x + threadIdx.x;   // 8-elt index
    const int e0  = idx << 3;
    const int n   = e0 >> 24;                 // I*S = 2^24 elements per n
    const int p   = e0 & (S - 1);
    const float inv = 1.f / (float)S;
    float m   = d_zstat[n] * inv;
    float var = fmaxf(d_zstat[NB + n] * inv - m * m, 0.f);
    float A   = gam_p[0] * rsqrtf(var + EPS);
    float B   = bet_p[0] - m * A;
    const float4* zp = reinterpret_cast<const float4*>(&d_z[n * S + p]);
    const float4* xp = reinterpret_cast<const float4*>(x + e0);
    float4 z0 = zp[0], z1 = zp[1];
    float4 x0 = xp[0], x1 = xp[1];
    float4 o0, o1;
    o0.x = x0.x / (1.f + __expf(-fmaf(A, z0.x, B)));
    o0.y = x0.y / (1.f + __expf(-fmaf(A, z0.y, B)));
    o0.z = x0.z / (1.f + __expf(-fmaf(A, z0.z, B)));
    o0.w = x0.w / (1.f + __expf(-fmaf(A, z0.w, B)));
    o1.x = x1.x / (1.f + __expf(-fmaf(A, z1.x, B)));
    o1.y = x1.y / (1.f + __expf(-fmaf(A, z1.y, B)));
    o1.z = x1.z / (1.f + __expf(-fmaf(A, z1.z, B)));
    o1.w = x1.w / (1.f + __expf(-fmaf(A, z1.w, B)));
    float4* op = reinterpret_cast<float4*>(out + e0);
    op[0] = o0;
    op[1] = o1;
}

// ============================================================================
extern "C" void kernel_launch(void* const* d_in, const int* in_sizes, int n_in,
                              void* d_out, int out_size) {
    const float* g     = (const float*)d_in[0];
    const float* x     = (const float*)d_in[1];
    const float* Wg    = (const float*)d_in[2];
    const float* Wx    = (const float*)d_in[3];
    const float* Wpsi  = (const float*)d_in[4];
    const float* gam_g = (const float*)d_in[5];
    const float* bet_g = (const float*)d_in[6];
    const float* gam_x = (const float*)d_in[7];
    const float* bet_x = (const float*)d_in[8];
    const float* gam_p = (const float*)d_in[9];
    const float* bet_p = (const float*)d_in[10];
    float* out = (float*)d_out;

    const int SMEM = 49152 + 32768 + 16384;        // 98304
    cudaFuncSetAttribute(k_gemm_fused,
                         cudaFuncAttributeMaxDynamicSharedMemorySize, SMEM);

    // launches 1-3: prologue + gemm, so k_combine is launch #4 (ncu slot)
    k_wconv_g<<<128, 256>>>(Wg);
    k_wconv_x_zero<<<64, 256>>>(Wx);

    dim3 ggrid(2048, NB);              // per n: 1024 x-tiles + 1024 g-tiles
    k_gemm_fused<<<ggrid, 256, SMEM>>>(g, x);

    dim3 cgrid(S / 2048, NB);                      // 64 x 2
    k_combine<<<cgrid, 256>>>(Wpsi, gam_g, bet_g, gam_x, bet_x);

    int total8 = NB * XC * S / 8;                  // 4,194,304 8-elt groups
    k_mul<<<total8 / 256, 256>>>(x, out, gam_p, bet_p);
}

// round 17
// speedup vs baseline: 1.1339x; 1.1339x over previous
#include <cuda_runtime.h>
#include <cuda_fp16.h>

// ============================================================================
// AttentionGate3D — round 17: round-13 (best, 244.2us) with k_combine
// re-parallelized per the measured scaling law (128 blk = 82us, 256 blk =
// ~40us -> latency-bound): 512 blocks, 2 pts/thread. GEMM + k_mul verbatim
// round 13. k_combine at ncu slot 4.
// ============================================================================

#define EPS 1e-5f

constexpr int NB = 2;
constexpr int G  = 256;
constexpr int XC = 128;
constexpr int I  = 128;
constexpr int S  = 32 * 64 * 64;   // 131072

// ---- scratch ----
__device__ __half d_yg[NB * I * S];
__device__ __half d_yx[NB * I * S];
__device__ __align__(16) __half d_whg[I * G];
__device__ __align__(16) __half d_whx[I * XC];
__device__ float  d_z[NB * S];
__device__ float  d_sum_g[NB * I];
__device__ float  d_sq_g [NB * I];
__device__ float  d_sum_x[NB * I];
__device__ float  d_sq_x [NB * I];
__device__ float  d_zstat[2 * NB];

// ---- prologue (2 launches; gemm=3rd, combine=4th = ncu slot) ----
__global__ void k_wconv_g(const float* __restrict__ Wg) {
    int t = blockIdx.x * 256 + threadIdx.x;
    if (t < I * G) d_whg[t] = __float2half_rn(Wg[t]);
}
__global__ void k_wconv_x_zero(const float* __restrict__ Wx) {
    int t = blockIdx.x * 256 + threadIdx.x;
    if (t < I * XC) d_whx[t] = __float2half_rn(Wx[t]);
    if (t < NB * I) {
        d_sum_g[t] = 0.f; d_sq_g[t] = 0.f;
        d_sum_x[t] = 0.f; d_sq_x[t] = 0.f;
    }
    if (t < 2 * NB) d_zstat[t] = 0.f;
}

// ---- MMA helpers ----
__device__ __forceinline__ void ldsm_x4(unsigned (&r)[4], unsigned addr) {
    asm volatile("ldmatrix.sync.aligned.m8n8.x4.shared.b16 {%0,%1,%2,%3}, [%4];"
        : "=r"(r[0]), "=r"(r[1]), "=r"(r[2]), "=r"(r[3]) : "r"(addr));
}
__device__ __forceinline__ void ldsm_x4_t(unsigned (&r)[4], unsigned addr) {
    asm volatile("ldmatrix.sync.aligned.m8n8.x4.trans.shared.b16 {%0,%1,%2,%3}, [%4];"
        : "=r"(r[0]), "=r"(r[1]), "=r"(r[2]), "=r"(r[3]) : "r"(addr));
}
__device__ __forceinline__ void mma16816(float (&d)[4], const unsigned (&a)[4],
                                         const unsigned (&b)[2]) {
    asm volatile("mma.sync.aligned.m16n8k16.row.col.f32.f16.f16.f32 "
        "{%0,%1,%2,%3}, {%4,%5,%6,%7}, {%8,%9}, {%0,%1,%2,%3};"
        : "+f"(d[0]), "+f"(d[1]), "+f"(d[2]), "+f"(d[3])
        : "r"(a[0]), "r"(a[1]), "r"(a[2]), "r"(a[3]), "r"(b[0]), "r"(b[1]));
}
union H2U { __half2 h; unsigned u; };
__device__ __forceinline__ unsigned pack2h(float a, float b) {
    H2U v; v.h = __floats2half2_rn(a, b); return v.u;
}
__device__ __forceinline__ void cp16(unsigned dst, const void* src) {
    asm volatile("cp.async.cg.shared.global [%0], [%1], 16;" :: "r"(dst), "l"(src));
}
__device__ __forceinline__ void cp_commit() {
    asm volatile("cp.async.commit_group;" ::: "memory");
}
template<int N>
__device__ __forceinline__ void cp_wait() {
    asm volatile("cp.async.wait_group %0;" :: "n"(N) : "memory");
}

// ---- GEMM body (round-9/13, verbatim) --------------------------------------
template<int K, bool ISG>
__device__ __forceinline__ void gemm_body(const float* __restrict__ src,
                                          char* smem, int n, int p0) {
    constexpr int NIT2 = K / 32;
    const unsigned sS32  = (unsigned)__cvta_generic_to_shared(smem);
    const unsigned sAh32 = (unsigned)__cvta_generic_to_shared(smem + 49152);
    const unsigned sBh32 = (unsigned)__cvta_generic_to_shared(smem + 81920);
    float*  sS  = reinterpret_cast<float*>(smem);
    __half* sBh = reinterpret_cast<__half*>(smem + 81920);

    const __half* wh  = ISG ? d_whg   : d_whx;
    __half* yout = ISG ? d_yg    : d_yx;
    float*  ssum = ISG ? d_sum_g : d_sum_x;
    float*  ssq  = ISG ? d_sq_g  : d_sq_x;

    const int tid  = threadIdx.x;
    const int warp = tid >> 5, lane = tid & 31;
    const int wm = warp >> 2, wn = warp & 3;
    const float* srcn = src + (size_t)n * K * S + p0;

    const int cst = tid >> 4;
    const int pb  = tid & 15;
    const float* gp = srcn + (size_t)cst * S + pb * 4;
    const unsigned myoffB = (unsigned)(cst * 512 + pb * 16);
    const int arow = tid >> 1, ah = tid & 1;
    const __half* wsrc = wh + (size_t)arow * K + ah * 8;
    const unsigned myoffA = (unsigned)(arow * 16);

    auto issue = [&](int it) {
        unsigned dstB = sS32 + (unsigned)((it % 3) * 16384) + myoffB;
        const float* s0 = gp + (size_t)it * 32 * S;
        cp16(dstB, s0);
        cp16(dstB + 256, s0 + 64);
        cp16(dstB + 8192, s0 + (size_t)16 * S);
        cp16(dstB + 8192 + 256, s0 + (size_t)16 * S + 64);
        unsigned dstA = sAh32 + (unsigned)((it & 3) * 8192) + myoffA;
        const __half* w0 = wsrc + it * 32;
        cp16(dstA + ah * 2048, w0);
        cp16(dstA + (2 + ah) * 2048, w0 + 16);
    };

    issue(0); cp_commit();
    issue(1); cp_commit();
    issue(2); cp_commit();

    float acc[4][4][4] = {};

    const int swz  = ((pb >> 1) ^ (cst & 7));
    const int sts0 = (cst * 128 + (swz << 3)       + ((pb & 1) << 2)) * 2;
    const int sts1 = (cst * 128 + ((8 + swz) << 3) + ((pb & 1) << 2)) * 2;

    for (int it = 0; it < NIT2; it++) {
        cp_wait<2>();
        const float4* rp = reinterpret_cast<const float4*>(
            sS + (it % 3) * 4096 + cst * 128 + pb * 4);
        float4 w0 = rp[0];
        float4 w1 = rp[16];
        float4 w2 = rp[512];
        float4 w3 = rp[528];
        {
            char* sb = reinterpret_cast<char*>(sBh) + (it & 1) * 8192;
            uint2 u;
            u.x = pack2h(w0.x, w0.y); u.y = pack2h(w0.z, w0.w);
            *reinterpret_cast<uint2*>(sb + sts0) = u;
            u.x = pack2h(w1.x, w1.y); u.y = pack2h(w1.z, w1.w);
            *reinterpret_cast<uint2*>(sb + sts1) = u;
            u.x = pack2h(w2.x, w2.y); u.y = pack2h(w2.z, w2.w);
            *reinterpret_cast<uint2*>(sb + 4096 + sts0) = u;
            u.x = pack2h(w3.x, w3.y); u.y = pack2h(w3.z, w3.w);
            *reinterpret_cast<uint2*>(sb + 4096 + sts1) = u;
        }
        __syncthreads();
        if (it + 3 < NIT2) issue(it + 3);
        cp_commit();

        const unsigned sbb = sBh32 + (unsigned)((it & 1) * 8192);
        const unsigned saa = sAh32 + (unsigned)((it & 3) * 8192);
#pragma unroll
        for (int kh2 = 0; kh2 < 2; kh2++) {
            unsigned afr[4][4];
#pragma unroll
            for (int tm = 0; tm < 4; tm++) {
                int row = wm * 64 + tm * 16 + (lane & 15);
                ldsm_x4(afr[tm], saa + (unsigned)(kh2 * 4096 +
                         (lane >> 4) * 2048 + row * 16));
            }
            unsigned bfr[4][2];
#pragma unroll
            for (int h = 0; h < 2; h++) {
                int nbX  = 2 * h + ((lane >> 4) & 1);
                int c    = ((lane >> 3) & 1) * 8 + (lane & 7);
                int phys = (wn * 4 + nbX) ^ (lane & 7);
                unsigned r4[4];
                ldsm_x4_t(r4, sbb + (unsigned)(kh2 * 4096 +
                          (c * 128 + phys * 8) * 2));
                bfr[2 * h][0]     = r4[0]; bfr[2 * h][1]     = r4[1];
                bfr[2 * h + 1][0] = r4[2]; bfr[2 * h + 1][1] = r4[3];
            }
#pragma unroll
            for (int tm = 0; tm < 4; tm++)
#pragma unroll
                for (int tn = 0; tn < 4; tn++)
                    mma16816(acc[tm][tn], afr[tm], bfr[tn]);
        }
    }

    __half* yn = yout + (size_t)n * I * S + p0;
#pragma unroll
    for (int tm = 0; tm < 4; tm++) {
        int r1 = wm * 64 + tm * 16 + (lane >> 2);
        float s1 = 0.f, q1 = 0.f, s2 = 0.f, q2 = 0.f;
#pragma unroll
        for (int tn = 0; tn < 4; tn++) {
            float* c = acc[tm][tn];
            int col = wn * 32 + tn * 8 + (lane & 3) * 2;
            *reinterpret_cast<__half2*>(yn + (size_t)r1 * S + col) =
                __floats2half2_rn(c[0], c[1]);
            *reinterpret_cast<__half2*>(yn + (size_t)(r1 + 8) * S + col) =
                __floats2half2_rn(c[2], c[3]);
            s1 += c[0] + c[1]; q1 += c[0] * c[0] + c[1] * c[1];
            s2 += c[2] + c[3]; q2 += c[2] * c[2] + c[3] * c[3];
        }
#pragma unroll
        for (int off = 2; off > 0; off >>= 1) {
            s1 += __shfl_down_sync(0xFFFFFFFFu, s1, off, 4);
            q1 += __shfl_down_sync(0xFFFFFFFFu, q1, off, 4);
            s2 += __shfl_down_sync(0xFFFFFFFFu, s2, off, 4);
            q2 += __shfl_down_sync(0xFFFFFFFFu, q2, off, 4);
        }
        if ((lane & 3) == 0) {
            atomicAdd(&ssum[n * I + r1], s1);
            atomicAdd(&ssq [n * I + r1], q1);
            atomicAdd(&ssum[n * I + r1 + 8], s2);
            atomicAdd(&ssq [n * I + r1 + 8], q2);
        }
    }
}

// ---- fused GEMM: even bx -> x-GEMM, odd bx -> g-GEMM (1024 tiles each) ----
__global__ void __launch_bounds__(256, 2) k_gemm_fused(const float* __restrict__ g,
                                                       const float* __restrict__ x) {
    extern __shared__ __align__(16) char smem[];
    const int bx = blockIdx.x;
    const int n  = blockIdx.y;
    const int p0 = (bx >> 1) * 128;
    if ((bx & 1) == 0) {
        gemm_body<XC, false>(x, smem, n, p0);
    } else {
        gemm_body<G, true>(g, smem, n, p0);
    }
}

// ---- combine: 512 blocks, 2 pts/thread (latency-scaling fix) ---------------
__global__ void __launch_bounds__(256) k_combine(
        const float* __restrict__ Wpsi,
        const float* __restrict__ gam_g, const float* __restrict__ bet_g,
        const float* __restrict__ gam_x, const float* __restrict__ bet_x) {
    __shared__ float sc[5 * I];
    const int tid = threadIdx.x;
    const int n   = blockIdx.y;
    const int p0  = blockIdx.x * 512;
    if (tid < I) {
        const float inv = 1.f / (float)S;
        float m   = d_sum_g[n * I + tid] * inv;
        float var = fmaxf(d_sq_g[n * I + tid] * inv - m * m, 0.f);
        float A   = gam_g[tid] * rsqrtf(var + EPS);
        sc[tid]     = A;
        sc[I + tid] = bet_g[tid] - m * A;
        m   = d_sum_x[n * I + tid] * inv;
        var = fmaxf(d_sq_x[n * I + tid] * inv - m * m, 0.f);
        A   = gam_x[tid] * rsqrtf(var + EPS);
        sc[2 * I + tid] = A;
        sc[3 * I + tid] = bet_x[tid] - m * A;
        sc[4 * I + tid] = Wpsi[tid];
    }
    __syncthreads();
    const __half* ygb = d_yg + (size_t)n * I * S + p0 + tid * 2;
    const __half* yxb = d_yx + (size_t)n * I * S + p0 + tid * 2;
    float za[2] = {0.f, 0.f};

#pragma unroll 8
    for (int i = 0; i < I; i++) {
        unsigned ua = *reinterpret_cast<const unsigned*>(ygb + (size_t)i * S);
        unsigned ub = *reinterpret_cast<const unsigned*>(yxb + (size_t)i * S);
        float Ag = sc[i], Ax = sc[2 * I + i];
        float C  = sc[I + i] + sc[3 * I + i];
        float w  = sc[4 * I + i];
        H2U ha, hb; ha.u = ua; hb.u = ub;
        float2 fa = __half22float2(ha.h);
        float2 fb = __half22float2(hb.h);
        za[0] += w * fmaxf(fmaf(Ag, fa.x, fmaf(Ax, fb.x, C)), 0.f);
        za[1] += w * fmaxf(fmaf(Ag, fa.y, fmaf(Ax, fb.y, C)), 0.f);
    }
    *reinterpret_cast<float2*>(&d_z[n * S + p0 + tid * 2]) =
        make_float2(za[0], za[1]);

    float s = za[0] + za[1];
    float q = za[0] * za[0] + za[1] * za[1];
#pragma unroll
    for (int off = 16; off > 0; off >>= 1) {
        s += __shfl_down_sync(0xFFFFFFFFu, s, off);
        q += __shfl_down_sync(0xFFFFFFFFu, q, off);
    }
    __shared__ float rs[8], rq[8];
    int wid = tid >> 5, ln = tid & 31;
    if (ln == 0) { rs[wid] = s; rq[wid] = q; }
    __syncthreads();
    if (tid == 0) {
        float st = 0.f, qt = 0.f;
#pragma unroll
        for (int w2 = 0; w2 < 8; w2++) { st += rs[w2]; qt += rq[w2]; }
        atomicAdd(&d_zstat[n], st);
        atomicAdd(&d_zstat[NB + n], qt);
    }
}

// ---- fused alpha+mul (round-13 exact) ---------------------------------------
__global__ void k_mul(const float* __restrict__ x, float* __restrict__ out,
                      const float* __restrict__ gam_p, const float* __restrict__ bet_p) {
    const int idx = blockIdx.x * blockDim.x + threadIdx.x;   // float4 index
    const int n   = idx >> 22;
    const int p4  = idx & (S / 4 - 1);
    const float inv = 1.f / (float)S;
    float m   = d_zstat[n] * inv;
    float var = fmaxf(d_zstat[NB + n] * inv - m * m, 0.f);
    float A   = gam_p[0] * rsqrtf(var + EPS);
    float B   = bet_p[0] - m * A;
    float4 z  = *reinterpret_cast<const float4*>(&d_z[n * S + p4 * 4]);
    float4 xv = reinterpret_cast<const float4*>(x)[idx];
    float4 o;
    o.x = xv.x / (1.f + __expf(-fmaf(A, z.x, B)));
    o.y = xv.y / (1.f + __expf(-fmaf(A, z.y, B)));
    o.z = xv.z / (1.f + __expf(-fmaf(A, z.z, B)));
    o.w = xv.w / (1.f + __expf(-fmaf(A, z.w, B)));
    reinterpret_cast<float4*>(out)[idx] = o;
}

// ============================================================================
extern "C" void kernel_launch(void* const* d_in, const int* in_sizes, int n_in,
                              void* d_out, int out_size) {
    const float* g     = (const float*)d_in[0];
    const float* x     = (const float*)d_in[1];
    const float* Wg    = (const float*)d_in[2];
    const float* Wx    = (const float*)d_in[3];
    const float* Wpsi  = (const float*)d_in[4];
    const float* gam_g = (const float*)d_in[5];
    const float* bet_g = (const float*)d_in[6];
    const float* gam_x = (const float*)d_in[7];
    const float* bet_x = (const float*)d_in[8];
    const float* gam_p = (const float*)d_in[9];
    const float* bet_p = (const float*)d_in[10];
    float* out = (float*)d_out;

    const int SMEM = 49152 + 32768 + 16384;        // 98304
    cudaFuncSetAttribute(k_gemm_fused,
                         cudaFuncAttributeMaxDynamicSharedMemorySize, SMEM);

    // launches 1-3: prologue + gemm, so k_combine is launch #4 (ncu slot)
    k_wconv_g<<<128, 256>>>(Wg);
    k_wconv_x_zero<<<64, 256>>>(Wx);

    dim3 ggrid(2048, NB);              // per n: 1024 x-tiles + 1024 g-tiles
    k_gemm_fused<<<ggrid, 256, SMEM>>>(g, x);

    dim3 cgrid(S / 512, NB);                       // 256 x 2 = 512 blocks
    k_combine<<<cgrid, 256>>>(Wpsi, gam_g, bet_g, gam_x, bet_x);

    int total4 = NB * XC * S / 4;                  // 16,777,216 float4
    k_mul<<<total4 / 256, 256>>>(x, out, gam_p, bet_p);
}